// round 16
// baseline (speedup 1.0000x reference)
#include <cuda_runtime.h>
#include <cuda_fp16.h>
#include <math.h>

// ---------------- problem constants ----------------
#define BB 4
#define CC 64
#define HH 128
#define WW 128
#define EE 32
#define HW (HH*WW)              // 16384
#define NPIX (BB*HW)            // 65536
#define PADW 130
#define PADIMG (PADW*PADW)      // 16900
#define NPADROW (BB*PADIMG)     // 67600
#define MAXTILES 1056
#define SLAB 65536              // per-expert assignment slab

// per-expert B fragments: 9 taps * 4 kc * 8 nb * 32 lanes uint2 {h0,h1}
#define WF2E 9216

// conv smem layout. A: 128 rows x 400B pitch; B: 2 x 8KB double buffer.
#define AHI_OFF 0u              // 51200
#define BF_OFF  51200u          // 2 x 8192 = 16384
#define PR_OFF  67584u          // int[128]
#define GW_OFF  68096u          // float[128]
#define BIAS_OFF 68608u         // float[64]
#define CONV_SMEM 68864u

// fused prep+gate block ranges
#define PB_TX   2048
#define PB_BRD  (PB_TX + 258)   // 2306
#define PB_TW   (PB_BRD + 1152) // 3458
#define PB_GATE (PB_TW + 256)   // 3714

// ---------------- device scratch ----------------
__device__ __half g_x_hi[NPADROW * CC];
__device__ uint2 g_wf2[EE * WF2E];
__device__ int   g_cursor[EE];           // zero-init at load; re-zeroed by k_comb
__device__ int   g_tileMap[MAXTILES];    // e<<10 | tileInExpert, -1 = empty
__device__ int   g_listPix[EE * SLAB];   // stores pixk = pix*2+k
__device__ float g_listW[EE * SLAB];
__device__ float g_scr[NPIX * 2 * CC];   // per-assignment results [pixk][64]

__device__ __forceinline__ unsigned short hfbits(__half h) {
    return *reinterpret_cast<unsigned short*>(&h);
}

// ---------------- fused prep: tx + border + tw + gate/scatter ----------------
__global__ void __launch_bounds__(256) k_prep(const float* __restrict__ x,
                                              const float* __restrict__ w,
                                              const float* __restrict__ gw,
                                              const float* __restrict__ gb) {
    int blk = blockIdx.x, tid = threadIdx.x;
    if (blk < PB_TX) {
        // transpose x -> padded channels-last fp16
        __shared__ float s[CC][33];
        int b = blk >> 9, hw0 = (blk & 511) << 5;
        int tx = tid & 31, ty = tid >> 5;
        for (int c = ty; c < CC; c += 8)
            s[c][tx] = x[((size_t)(b * CC + c) << 14) + hw0 + tx];
        __syncthreads();
        int y = hw0 >> 7, x0 = hw0 & 127;
        unsigned* hi32 = (unsigned*)g_x_hi;
        for (int k = tid; k < 32 * 32; k += 256) {
            int p = k >> 5, cp = k & 31;
            int row = b * PADIMG + (y + 1) * PADW + (x0 + p + 1);
            __half ha = __float2half_rn(s[2 * cp][p]);
            __half hb = __float2half_rn(s[2 * cp + 1][p]);
            hi32[row * 32 + cp] = ((unsigned)hfbits(hb) << 16) | hfbits(ha);
        }
    } else if (blk < PB_BRD) {
        // zero halo rows
        int u = (blk - PB_TX) * 256 + tid;
        if (u < 2064 * 32) {
            int word = u & 31;
            int p = u >> 5;
            int b = p / 516, r = p % 516;
            int y, xx;
            if (r < 130)      { y = 0;           xx = r; }
            else if (r < 260) { y = 129;         xx = r - 130; }
            else if (r < 388) { y = r - 260 + 1; xx = 0; }
            else              { y = r - 388 + 1; xx = 129; }
            int row = b * PADIMG + y * PADW + xx;
            ((unsigned*)g_x_hi)[row * 32 + word] = 0u;
        }
    } else if (blk < PB_TW) {
        // weights -> pre-permuted fp16 B fragments {h(k0,k1), h(k8,k9)}
        int i = (blk - PB_BRD) * 256 + tid;
        int e = i / WF2E;
        int r = i % WF2E;
        int t = r >> 10;  r &= 1023;
        int kc = r >> 8;  r &= 255;
        int nb = r >> 5;
        int lane = r & 31;
        int co  = nb * 8 + (lane >> 2);
        int ci0 = kc * 16 + 2 * (lane & 3);
        const float* wp = w + (size_t)(((e << 6) | co) << 6) * 9 + t;
        __half h00 = __float2half_rn(wp[(ci0)     * 9]);
        __half h01 = __float2half_rn(wp[(ci0 + 1) * 9]);
        __half h10 = __float2half_rn(wp[(ci0 + 8) * 9]);
        __half h11 = __float2half_rn(wp[(ci0 + 9) * 9]);
        uint2 o;
        o.x = ((unsigned)hfbits(h01) << 16) | hfbits(h00);
        o.y = ((unsigned)hfbits(h11) << 16) | hfbits(h10);
        g_wf2[i] = o;
    } else {
        // gate + scatter (independent of the other phases)
        __shared__ float gws[EE * CC];
        __shared__ float gbs[EE];
        __shared__ float xs[16][256];
        for (int i = tid; i < EE * CC; i += 256) gws[i] = gw[i];
        if (tid < EE) gbs[tid] = gb[tid];

        int pix0 = (blk - PB_TW) * 256;
        int b = pix0 >> 14, hw0 = pix0 & (HW - 1);

        float lg[EE];
#pragma unroll
        for (int e = 0; e < EE; e++) lg[e] = 0.0f;

        for (int c0 = 0; c0 < CC; c0 += 16) {
            __syncthreads();
            for (int i = tid; i < 16 * 256; i += 256)
                xs[i >> 8][tid] = x[((size_t)(b * CC + c0 + (i >> 8)) << 14) + hw0 + tid];
            __syncthreads();
#pragma unroll 4
            for (int c = 0; c < 16; c++) {
                float xv = xs[c][tid];
#pragma unroll
                for (int e = 0; e < EE; e++)
                    lg[e] = fmaf(xv, gws[(e << 6) + c0 + c], lg[e]);
            }
        }
#pragma unroll
        for (int e = 0; e < EE; e++) lg[e] += gbs[e];

        // exact top-2, first-index-on-tie (matches lax.top_k)
        float v1 = -1e30f; int i1 = 0;
#pragma unroll
        for (int e = 0; e < EE; e++) if (lg[e] > v1) { v1 = lg[e]; i1 = e; }
        float v2 = -1e30f; int i2 = 0;
#pragma unroll
        for (int e = 0; e < EE; e++) if (e != i1 && lg[e] > v2) { v2 = lg[e]; i2 = e; }

        float d = expf(v2 - v1);
        float s = 1.0f / (1.0f + d);
        int pix = pix0 + tid;
        int p1 = atomicAdd(&g_cursor[i1], 1);
        g_listPix[i1 * SLAB + p1] = pix * 2;
        g_listW[i1 * SLAB + p1]  = s;
        int p2 = atomicAdd(&g_cursor[i2], 1);
        g_listPix[i2 * SLAB + p2] = pix * 2 + 1;
        g_listW[i2 * SLAB + p2]  = d * s;
    }
}

// ---------------- plan: tile -> (expert, tileInExpert) map ----------------
__global__ void k_plan() {
    int e = threadIdx.x;                     // one warp
    int cnt = (e < EE) ? g_cursor[e] : 0;
    int nt = (cnt + 127) >> 7;
    // inclusive warp scan of nt
    int s = nt;
#pragma unroll
    for (int off = 1; off < 32; off <<= 1) {
        int v = __shfl_up_sync(0xffffffffu, s, off);
        if (e >= off) s += v;
    }
    int start = s - nt;
    for (int i = 0; i < nt; i++)
        g_tileMap[start + i] = (e << 10) | i;
    int total = __shfl_sync(0xffffffffu, s, 31);
    for (int i = total + e; i < MAXTILES; i += 32)
        g_tileMap[i] = -1;
}

// ---------------- main conv: fp16 single-pass, A 3-phase + B smem double-buffer ----------------
#define MMA(c, a, b0, b1) \
    asm volatile("mma.sync.aligned.m16n8k16.row.col.f32.f16.f16.f32 " \
        "{%0,%1,%2,%3}, {%4,%5,%6,%7}, {%8,%9}, {%0,%1,%2,%3};" \
        : "+f"((c)[0]), "+f"((c)[1]), "+f"((c)[2]), "+f"((c)[3]) \
        : "r"((a)[0]), "r"((a)[1]), "r"((a)[2]), "r"((a)[3]), "r"(b0), "r"(b1))

#define LDSM4(r, addr) \
    asm volatile("ldmatrix.sync.aligned.m8n8.x4.shared.b16 {%0,%1,%2,%3}, [%4];" \
        : "=r"((r)[0]), "=r"((r)[1]), "=r"((r)[2]), "=r"((r)[3]) : "r"(addr))

#define CPA16(dst, src) \
    asm volatile("cp.async.cg.shared.global [%0], [%1], 16;" :: "r"(dst), "l"(src))

__global__ void __launch_bounds__(256, 3)
k_conv(const float* __restrict__ expert_b) {
    extern __shared__ char sm[];
    const int tid = threadIdx.x, warp = tid >> 5, lane = tid & 31;

    int v = g_tileMap[blockIdx.x];
    if (v < 0) return;
    int e  = v >> 10;
    int r0 = (v & 1023) << 7;
    int m  = g_cursor[e] - r0; if (m > 128) m = 128;
    int lb = e * SLAB + r0;

    if (tid < 128) {
        int valid = tid < m;
        int idx = lb + (valid ? tid : 0);
        int pixk = g_listPix[idx];
        float gv = valid ? g_listW[idx] : 0.0f;
        int row = PADW + 1;   // interior (0,0): all windows in-bounds
        if (valid) {
            int pix = pixk >> 1;
            int b = pix >> 14, hw = pix & (HW - 1);
            row = b * PADIMG + ((hw >> 7) + 1) * PADW + ((hw & 127) + 1);
        }
        ((int*)(sm + PR_OFF))[tid]   = row;
        ((float*)(sm + GW_OFF))[tid] = gv;
    }
    if (tid < 64) ((float*)(sm + BIAS_OFF))[tid] = expert_b[(e << 6) + tid];
    __syncthreads();

    const int myrow = tid >> 1, half = tid & 1;
    const int rbase = ((int*)(sm + PR_OFF))[myrow];
    const uint2* __restrict__ wf = g_wf2 + (size_t)e * WF2E;
    unsigned smb = (unsigned)__cvta_generic_to_shared(sm);

    unsigned aDst = smb + AHI_OFF + myrow * 400 + half * 192;
    unsigned bDst = smb + BF_OFF + tid * 16;

    // 4m x 2n warp split
    const int mt2 = warp & 3, nw = warp >> 2;
    float c[2][4][4];
#pragma unroll
    for (int h = 0; h < 2; h++)
#pragma unroll
        for (int nb = 0; nb < 4; nb++)
#pragma unroll
            for (int j = 0; j < 4; j++) c[h][nb][j] = 0.0f;

    unsigned aB0 = smb + AHI_OFF + ((mt2 << 5) + (lane & 15)) * 400 + ((lane >> 4) << 4);
    unsigned aB1 = aB0 + 16 * 400;

    // ---- stage issuers ----
    auto issueA = [&](int dy) {
        const char* src = (const char*)g_x_hi
            + (((size_t)(rbase + (dy - 1) * PADW - 1)) << 7) + half * 192;
#pragma unroll
        for (int i = 0; i < 12; i++)
            CPA16(aDst + i * 16, src + i * 16);
        asm volatile("cp.async.commit_group;");
    };
    auto issueB = [&](int t) {
        const char* src = (const char*)(wf + (t << 10)) + tid * 16;
        unsigned dB = bDst + (unsigned)(t & 1) * 8192u;
#pragma unroll
        for (int i = 0; i < 2; i++)
            CPA16(dB + i * 4096, src + i * 4096);
        asm volatile("cp.async.commit_group;");
    };

    // prologue: A(dy=0) + B(0)
    issueA(0);
    issueB(0);

#pragma unroll 1
    for (int t = 0; t < 9; t++) {
        int dy = t / 3, dx = t - dy * 3;
        if (dx == 0 && t > 0) {
            __syncthreads();        // A(dy-1) fully consumed
            issueA(dy);
        }
        asm volatile("cp.async.wait_group 0;");
        __syncthreads();
        if (t < 8) issueB(t + 1);   // prefetch next tap's B into other buffer

        const uint2* bp0 = (const uint2*)(sm + BF_OFF + (unsigned)(t & 1) * 8192u)
                         + (nw << 7) + lane;
#pragma unroll
        for (int kc = 0; kc < 4; kc++) {
            unsigned ah0[4], ah1[4];
            LDSM4(ah0, aB0 + dx * 128 + kc * 32);
            LDSM4(ah1, aB1 + dx * 128 + kc * 32);
            const uint2* bp = bp0 + (kc << 8);
#pragma unroll
            for (int nb = 0; nb < 4; nb++) {
                uint2 bb = bp[nb << 5];
                MMA(c[0][nb], ah0, bb.x, bb.y);
                MMA(c[1][nb], ah1, bb.x, bb.y);
            }
        }
    }

    // ---- epilogue: plain stores of gw*(acc+bias) into per-assignment scratch ----
    {
        const float* bias = (const float*)(sm + BIAS_OFF);
        int i4 = lane & 3;
#pragma unroll
        for (int h = 0; h < 2; h++) {
            int r1 = (mt2 << 5) + (h << 4) + (lane >> 2), r2 = r1 + 8;
            bool v1 = r1 < m, v2 = r2 < m;
            int pk1 = v1 ? g_listPix[lb + r1] : 0;
            int pk2 = v2 ? g_listPix[lb + r2] : 0;
            float gw1 = ((float*)(sm + GW_OFF))[r1];
            float gw2 = ((float*)(sm + GW_OFF))[r2];
            float* sp1 = g_scr + ((size_t)pk1 << 6);
            float* sp2 = g_scr + ((size_t)pk2 << 6);
#pragma unroll
            for (int nb = 0; nb < 4; nb++) {
                int co = ((nw << 2) + nb) * 8 + 2 * i4;
                if (v1)
                    *(float2*)(sp1 + co) = make_float2(gw1 * (c[h][nb][0] + bias[co]),
                                                       gw1 * (c[h][nb][1] + bias[co + 1]));
                if (v2)
                    *(float2*)(sp2 + co) = make_float2(gw2 * (c[h][nb][2] + bias[co]),
                                                       gw2 * (c[h][nb][3] + bias[co + 1]));
            }
        }
    }
}

// ---------------- combine: sum 2 slots, relu, transpose to NCHW; re-zero counters ----------------
__global__ void __launch_bounds__(256) k_comb(float* __restrict__ out) {
    __shared__ float s[64][68];
    int tid = threadIdx.x;
    // re-zero per-expert counters for the NEXT graph replay
    if (blockIdx.x == 0 && tid < EE) g_cursor[tid] = 0;

    int pix0 = blockIdx.x << 6;
    int b = pix0 >> 14, hw0 = pix0 & (HW - 1);

    {
        int p = tid >> 2, c4 = (tid & 3) << 4;
        const float4* s0 = (const float4*)(g_scr + ((size_t)(pix0 + p) << 7)) + (c4 >> 2);
        const float4* s1 = (const float4*)(g_scr + ((size_t)(pix0 + p) << 7) + 64) + (c4 >> 2);
#pragma unroll
        for (int i = 0; i < 4; i++) {
            float4 a = s0[i], bv = s1[i];
            s[c4 + 4 * i + 0][p] = fmaxf(a.x + bv.x, 0.0f);
            s[c4 + 4 * i + 1][p] = fmaxf(a.y + bv.y, 0.0f);
            s[c4 + 4 * i + 2][p] = fmaxf(a.z + bv.z, 0.0f);
            s[c4 + 4 * i + 3][p] = fmaxf(a.w + bv.w, 0.0f);
        }
    }
    __syncthreads();
    {
        int c = tid >> 2, p4 = (tid & 3) << 4;
        float* op = out + ((size_t)((b << 6) + c) << 14) + hw0 + p4;
#pragma unroll
        for (int i = 0; i < 4; i++)
            *(float4*)(op + 4 * i) = *(float4*)&s[c][p4 + 4 * i];
    }
}

extern "C" void kernel_launch(void* const* d_in, const int* in_sizes, int n_in,
                              void* d_out, int out_size) {
    const float* x        = (const float*)d_in[0];
    const float* expert_w = (const float*)d_in[1];
    const float* expert_b = (const float*)d_in[2];
    const float* gate_w   = (const float*)d_in[3];
    const float* gate_b   = (const float*)d_in[4];
    float* out = (float*)d_out;

    cudaFuncSetAttribute(k_conv, cudaFuncAttributeMaxDynamicSharedMemorySize,
                         CONV_SMEM);

    k_prep<<<PB_GATE, 256>>>(x, expert_w, gate_w, gate_b);
    k_plan<<<1, 32>>>();
    k_conv<<<MAXTILES, 256, CONV_SMEM>>>(expert_b);
    k_comb<<<NPIX / 64, 256>>>(out);
}

// round 17
// speedup vs baseline: 1.0419x; 1.0419x over previous
#include <cuda_runtime.h>
#include <cuda_fp16.h>
#include <math.h>

// ---------------- problem constants ----------------
#define BB 4
#define CC 64
#define HH 128
#define WW 128
#define EE 32
#define HW (HH*WW)              // 16384
#define NPIX (BB*HW)            // 65536
#define PADW 130
#define PADIMG (PADW*PADW)      // 16900
#define NPADROW (BB*PADIMG)     // 67600
#define MAXTILES 1056
#define CONV_GRID 444           // 148 SMs x 3 resident CTAs
#define SLAB 65536              // per-expert assignment slab

// per-expert B fragments: 9 taps * 4 kc * 8 nb * 32 lanes uint2 {h0,h1}
#define WF2E 9216

// conv smem layout. A: 128 rows x 400B pitch; B: 2 x 8KB double buffer.
#define AHI_OFF 0u              // 51200
#define BF_OFF  51200u          // 2 x 8192 = 16384
#define PR_OFF  67584u          // int[128]
#define GW_OFF  68096u          // float[128]
#define BIAS_OFF 68608u         // float[64]
#define CONV_SMEM 68864u

// prep phase block ranges
#define PB_TX   2048
#define PB_BRD  (PB_TX + 258)   // 2306
#define PB_ALL  (PB_BRD + 1152) // 3458

// ---------------- device scratch ----------------
__device__ __half g_x_hi[NPADROW * CC];
__device__ uint2 g_wf2[EE * WF2E];
__device__ int   g_cursor[EE];           // zero-init at load; re-zeroed by k_comb
__device__ int   g_tileMap[MAXTILES];    // e<<10 | tileInExpert, -1 = empty
__device__ int   g_listPix[EE * SLAB];   // stores pixk = pix*2+k
__device__ float g_listW[EE * SLAB];
__device__ float g_scr[NPIX * 2 * CC];   // per-assignment results [pixk][64]

__device__ __forceinline__ unsigned short hfbits(__half h) {
    return *reinterpret_cast<unsigned short*>(&h);
}

// ---------------- fused prep: tx + border + tw ----------------
__global__ void __launch_bounds__(256) k_prep(const float* __restrict__ x,
                                              const float* __restrict__ w) {
    int blk = blockIdx.x, tid = threadIdx.x;
    if (blk < PB_TX) {
        // transpose x -> padded channels-last fp16
        __shared__ float s[CC][33];
        int b = blk >> 9, hw0 = (blk & 511) << 5;
        int tx = tid & 31, ty = tid >> 5;
        for (int c = ty; c < CC; c += 8)
            s[c][tx] = x[((size_t)(b * CC + c) << 14) + hw0 + tx];
        __syncthreads();
        int y = hw0 >> 7, x0 = hw0 & 127;
        unsigned* hi32 = (unsigned*)g_x_hi;
        for (int k = tid; k < 32 * 32; k += 256) {
            int p = k >> 5, cp = k & 31;
            int row = b * PADIMG + (y + 1) * PADW + (x0 + p + 1);
            __half ha = __float2half_rn(s[2 * cp][p]);
            __half hb = __float2half_rn(s[2 * cp + 1][p]);
            hi32[row * 32 + cp] = ((unsigned)hfbits(hb) << 16) | hfbits(ha);
        }
    } else if (blk < PB_BRD) {
        // zero halo rows
        int u = (blk - PB_TX) * 256 + tid;
        if (u < 2064 * 32) {
            int word = u & 31;
            int p = u >> 5;
            int b = p / 516, r = p % 516;
            int y, xx;
            if (r < 130)      { y = 0;           xx = r; }
            else if (r < 260) { y = 129;         xx = r - 130; }
            else if (r < 388) { y = r - 260 + 1; xx = 0; }
            else              { y = r - 388 + 1; xx = 129; }
            int row = b * PADIMG + y * PADW + xx;
            ((unsigned*)g_x_hi)[row * 32 + word] = 0u;
        }
    } else {
        // weights -> pre-permuted fp16 B fragments {h(k0,k1), h(k8,k9)}
        int i = (blk - PB_BRD) * 256 + tid;
        int e = i / WF2E;
        int r = i % WF2E;
        int t = r >> 10;  r &= 1023;
        int kc = r >> 8;  r &= 255;
        int nb = r >> 5;
        int lane = r & 31;
        int co  = nb * 8 + (lane >> 2);
        int ci0 = kc * 16 + 2 * (lane & 3);
        const float* wp = w + (size_t)(((e << 6) | co) << 6) * 9 + t;
        __half h00 = __float2half_rn(wp[(ci0)     * 9]);
        __half h01 = __float2half_rn(wp[(ci0 + 1) * 9]);
        __half h10 = __float2half_rn(wp[(ci0 + 8) * 9]);
        __half h11 = __float2half_rn(wp[(ci0 + 9) * 9]);
        uint2 o;
        o.x = ((unsigned)hfbits(h01) << 16) | hfbits(h00);
        o.y = ((unsigned)hfbits(h11) << 16) | hfbits(h10);
        g_wf2[i] = o;
    }
}

// ---------------- gate + fused scatter (appends pixk) ----------------
__global__ void __launch_bounds__(256) k_gate(const float* __restrict__ x,
                                              const float* __restrict__ gw,
                                              const float* __restrict__ gb) {
    __shared__ float gws[EE * CC];
    __shared__ float gbs[EE];
    __shared__ float xs[16][256];
    int tid = threadIdx.x;
    for (int i = tid; i < EE * CC; i += 256) gws[i] = gw[i];
    if (tid < EE) gbs[tid] = gb[tid];

    int pix0 = blockIdx.x * 256;
    int b = pix0 >> 14, hw0 = pix0 & (HW - 1);

    float lg[EE];
#pragma unroll
    for (int e = 0; e < EE; e++) lg[e] = 0.0f;

    for (int c0 = 0; c0 < CC; c0 += 16) {
        __syncthreads();
        for (int i = tid; i < 16 * 256; i += 256)
            xs[i >> 8][tid] = x[((size_t)(b * CC + c0 + (i >> 8)) << 14) + hw0 + tid];
        __syncthreads();
#pragma unroll 4
        for (int c = 0; c < 16; c++) {
            float xv = xs[c][tid];
#pragma unroll
            for (int e = 0; e < EE; e++)
                lg[e] = fmaf(xv, gws[(e << 6) + c0 + c], lg[e]);
        }
    }
#pragma unroll
    for (int e = 0; e < EE; e++) lg[e] += gbs[e];

    // exact top-2, first-index-on-tie (matches lax.top_k)
    float v1 = -1e30f; int i1 = 0;
#pragma unroll
    for (int e = 0; e < EE; e++) if (lg[e] > v1) { v1 = lg[e]; i1 = e; }
    float v2 = -1e30f; int i2 = 0;
#pragma unroll
    for (int e = 0; e < EE; e++) if (e != i1 && lg[e] > v2) { v2 = lg[e]; i2 = e; }

    float d = expf(v2 - v1);
    float s = 1.0f / (1.0f + d);
    int pix = pix0 + tid;
    int p1 = atomicAdd(&g_cursor[i1], 1);
    g_listPix[i1 * SLAB + p1] = pix * 2;
    g_listW[i1 * SLAB + p1]  = s;
    int p2 = atomicAdd(&g_cursor[i2], 1);
    g_listPix[i2 * SLAB + p2] = pix * 2 + 1;
    g_listW[i2 * SLAB + p2]  = d * s;
}

// ---------------- plan: tile -> (expert, tileInExpert) map ----------------
__global__ void k_plan() {
    int e = threadIdx.x;                     // one warp
    int cnt = (e < EE) ? g_cursor[e] : 0;
    int nt = (cnt + 127) >> 7;
    int s = nt;
#pragma unroll
    for (int off = 1; off < 32; off <<= 1) {
        int v = __shfl_up_sync(0xffffffffu, s, off);
        if (e >= off) s += v;
    }
    int start = s - nt;
    for (int i = 0; i < nt; i++)
        g_tileMap[start + i] = (e << 10) | i;
    int total = __shfl_sync(0xffffffffu, s, 31);
    for (int i = total + e; i < MAXTILES; i += 32)
        g_tileMap[i] = -1;
}

// ---------------- main conv: persistent, fp16 single-pass ----------------
#define MMA(c, a, b0, b1) \
    asm volatile("mma.sync.aligned.m16n8k16.row.col.f32.f16.f16.f32 " \
        "{%0,%1,%2,%3}, {%4,%5,%6,%7}, {%8,%9}, {%0,%1,%2,%3};" \
        : "+f"((c)[0]), "+f"((c)[1]), "+f"((c)[2]), "+f"((c)[3]) \
        : "r"((a)[0]), "r"((a)[1]), "r"((a)[2]), "r"((a)[3]), "r"(b0), "r"(b1))

#define LDSM4(r, addr) \
    asm volatile("ldmatrix.sync.aligned.m8n8.x4.shared.b16 {%0,%1,%2,%3}, [%4];" \
        : "=r"((r)[0]), "=r"((r)[1]), "=r"((r)[2]), "=r"((r)[3]) : "r"(addr))

#define CPA16(dst, src) \
    asm volatile("cp.async.cg.shared.global [%0], [%1], 16;" :: "r"(dst), "l"(src))

__global__ void __launch_bounds__(256, 3)
k_conv(const float* __restrict__ expert_b) {
    extern __shared__ char sm[];
    const int tid = threadIdx.x, warp = tid >> 5, lane = tid & 31;
    const int mt2 = warp & 3, nw = warp >> 2;
    unsigned smb = (unsigned)__cvta_generic_to_shared(sm);

    const int myrow = tid >> 1, half = tid & 1;
    unsigned aDst = smb + AHI_OFF + myrow * 400 + half * 192;
    unsigned bDst = smb + BF_OFF + tid * 16;
    unsigned aB0  = smb + AHI_OFF + ((mt2 << 5) + (lane & 15)) * 400 + ((lane >> 4) << 4);
    unsigned aB1  = aB0 + 16 * 400;

#pragma unroll 1
    for (int tile = blockIdx.x; tile < MAXTILES; tile += CONV_GRID) {
        int v = g_tileMap[tile];
        if (v < 0) break;                    // empties are at the tail
        int e  = v >> 10;
        int r0 = (v & 1023) << 7;
        int m  = g_cursor[e] - r0; if (m > 128) m = 128;
        int lb = e * SLAB + r0;

        if (tid < 128) {
            int valid = tid < m;
            int idx = lb + (valid ? tid : 0);
            int pixk = g_listPix[idx];
            float gv = valid ? g_listW[idx] : 0.0f;
            int row = PADW + 1;   // interior (0,0): all windows in-bounds
            if (valid) {
                int pix = pixk >> 1;
                int b = pix >> 14, hw = pix & (HW - 1);
                row = b * PADIMG + ((hw >> 7) + 1) * PADW + ((hw & 127) + 1);
            }
            ((int*)(sm + PR_OFF))[tid]   = row;
            ((float*)(sm + GW_OFF))[tid] = gv;
        }
        if (tid < 64) ((float*)(sm + BIAS_OFF))[tid] = expert_b[(e << 6) + tid];
        __syncthreads();

        const int rbase = ((int*)(sm + PR_OFF))[myrow];
        const uint2* __restrict__ wf = g_wf2 + (size_t)e * WF2E;

        float c[2][4][4];
#pragma unroll
        for (int h = 0; h < 2; h++)
#pragma unroll
            for (int nb = 0; nb < 4; nb++)
#pragma unroll
                for (int j = 0; j < 4; j++) c[h][nb][j] = 0.0f;

        // ---- stage issuers ----
        auto issueA = [&](int dy) {
            const char* src = (const char*)g_x_hi
                + (((size_t)(rbase + (dy - 1) * PADW - 1)) << 7) + half * 192;
#pragma unroll
            for (int i = 0; i < 12; i++)
                CPA16(aDst + i * 16, src + i * 16);
            asm volatile("cp.async.commit_group;");
        };
        auto issueB = [&](int t) {
            const char* src = (const char*)(wf + (t << 10)) + tid * 16;
            unsigned dB = bDst + (unsigned)(t & 1) * 8192u;
#pragma unroll
            for (int i = 0; i < 2; i++)
                CPA16(dB + i * 4096, src + i * 4096);
            asm volatile("cp.async.commit_group;");
        };

        issueA(0);
        issueB(0);

#pragma unroll 1
        for (int t = 0; t < 9; t++) {
            int dy = t / 3, dx = t - dy * 3;
            if (dx == 0 && t > 0) {
                __syncthreads();        // A(dy-1) fully consumed
                issueA(dy);
            }
            asm volatile("cp.async.wait_group 0;");
            __syncthreads();
            if (t < 8) issueB(t + 1);

            const uint2* bp0 = (const uint2*)(sm + BF_OFF + (unsigned)(t & 1) * 8192u)
                             + (nw << 7) + lane;
#pragma unroll
            for (int kc = 0; kc < 4; kc++) {
                unsigned ah0[4], ah1[4];
                LDSM4(ah0, aB0 + dx * 128 + kc * 32);
                LDSM4(ah1, aB1 + dx * 128 + kc * 32);
                const uint2* bp = bp0 + (kc << 8);
#pragma unroll
                for (int nb = 0; nb < 4; nb++) {
                    uint2 bb = bp[nb << 5];
                    MMA(c[0][nb], ah0, bb.x, bb.y);
                    MMA(c[1][nb], ah1, bb.x, bb.y);
                }
            }
        }

        // ---- epilogue ----
        {
            const float* bias = (const float*)(sm + BIAS_OFF);
            int i4 = lane & 3;
#pragma unroll
            for (int h = 0; h < 2; h++) {
                int r1 = (mt2 << 5) + (h << 4) + (lane >> 2), r2 = r1 + 8;
                bool v1 = r1 < m, v2 = r2 < m;
                int pk1 = v1 ? g_listPix[lb + r1] : 0;
                int pk2 = v2 ? g_listPix[lb + r2] : 0;
                float gw1 = ((float*)(sm + GW_OFF))[r1];
                float gw2 = ((float*)(sm + GW_OFF))[r2];
                float* sp1 = g_scr + ((size_t)pk1 << 6);
                float* sp2 = g_scr + ((size_t)pk2 << 6);
#pragma unroll
                for (int nb = 0; nb < 4; nb++) {
                    int co = ((nw << 2) + nb) * 8 + 2 * i4;
                    if (v1)
                        *(float2*)(sp1 + co) = make_float2(gw1 * (c[h][nb][0] + bias[co]),
                                                           gw1 * (c[h][nb][1] + bias[co + 1]));
                    if (v2)
                        *(float2*)(sp2 + co) = make_float2(gw2 * (c[h][nb][2] + bias[co]),
                                                           gw2 * (c[h][nb][3] + bias[co + 1]));
                }
            }
        }
        __syncthreads();   // metadata smem safe to overwrite next iteration
    }
}

// ---------------- combine: sum 2 slots, relu, transpose to NCHW; re-zero counters ----------------
__global__ void __launch_bounds__(256) k_comb(float* __restrict__ out) {
    __shared__ float s[64][68];
    int tid = threadIdx.x;
    if (blockIdx.x == 0 && tid < EE) g_cursor[tid] = 0;   // for next graph replay

    int pix0 = blockIdx.x << 6;
    int b = pix0 >> 14, hw0 = pix0 & (HW - 1);

    {
        int p = tid >> 2, c4 = (tid & 3) << 4;
        const float4* s0 = (const float4*)(g_scr + ((size_t)(pix0 + p) << 7)) + (c4 >> 2);
        const float4* s1 = (const float4*)(g_scr + ((size_t)(pix0 + p) << 7) + 64) + (c4 >> 2);
#pragma unroll
        for (int i = 0; i < 4; i++) {
            float4 a = s0[i], bv = s1[i];
            s[c4 + 4 * i + 0][p] = fmaxf(a.x + bv.x, 0.0f);
            s[c4 + 4 * i + 1][p] = fmaxf(a.y + bv.y, 0.0f);
            s[c4 + 4 * i + 2][p] = fmaxf(a.z + bv.z, 0.0f);
            s[c4 + 4 * i + 3][p] = fmaxf(a.w + bv.w, 0.0f);
        }
    }
    __syncthreads();
    {
        int c = tid >> 2, p4 = (tid & 3) << 4;
        float* op = out + ((size_t)((b << 6) + c) << 14) + hw0 + p4;
#pragma unroll
        for (int i = 0; i < 4; i++)
            *(float4*)(op + 4 * i) = *(float4*)&s[c][p4 + 4 * i];
    }
}

extern "C" void kernel_launch(void* const* d_in, const int* in_sizes, int n_in,
                              void* d_out, int out_size) {
    const float* x        = (const float*)d_in[0];
    const float* expert_w = (const float*)d_in[1];
    const float* expert_b = (const float*)d_in[2];
    const float* gate_w   = (const float*)d_in[3];
    const float* gate_b   = (const float*)d_in[4];
    float* out = (float*)d_out;

    cudaFuncSetAttribute(k_conv, cudaFuncAttributeMaxDynamicSharedMemorySize,
                         CONV_SMEM);

    k_prep<<<PB_ALL, 256>>>(x, expert_w);
    k_gate<<<NPIX / 256, 256>>>(x, gate_w, gate_b);
    k_plan<<<1, 32>>>();
    k_conv<<<CONV_GRID, 256, CONV_SMEM>>>(expert_b);   // launch #4 -> profiled
    k_comb<<<NPIX / 64, 256>>>(out);
}